// round 4
// baseline (speedup 1.0000x reference)
#include <cuda_runtime.h>
#include <cuda_bf16.h>
#include <cstdint>

// ===================== problem constants =====================
// x: 262144 rows x 128 (row = (b,i,r,p,g)); W: (8,128,128); b: (8,128)
// Job: 128 rows (M) x 128 cols (N) x K=128. Channel constant per 2 jobs.
#define N_DIM      128
#define K_DIM      128
#define ROWS_CTA   128
#define THREADS    256
#define NUM_JOBS   2048
#define GRID       304            // persistent: 2 CTAs x 152 SMs (GB300)
#define K_CHUNK    32
#define NCHUNK     4
#define STAGES     3

// ---- smem layout (floats) ----
#define SA_STRIDE  36                          // 36 mod 32 == 4 -> conflict-free frag reads
#define SA_FLOATS  (128 * SA_STRIDE)           // 4608
#define SW_FLOATS  4096                        // W chunk fragment image: 128 x 32
#define STAGE_FLOATS (SA_FLOATS + SW_FLOATS)   // 8704
#define SM_BIAS_OFF  (STAGES * STAGE_FLOATS)   // 26112
#define SMEM_FLOATS  (SM_BIAS_OFF + 8 * 128)   // all-channel bias
#define SMEM_BYTES   (SMEM_FLOATS * 4)         // 108,544

// ===================== helpers =====================
__device__ __forceinline__ uint32_t smem_u32(const void* p) {
    uint32_t a;
    asm("{ .reg .u64 t; cvta.to.shared.u64 t, %1; cvt.u32.u64 %0, t; }" : "=r"(a) : "l"(p));
    return a;
}
__device__ __forceinline__ uint32_t rna_tf32_u(float f) {
    uint32_t r;
    asm("cvt.rna.tf32.f32 %0, %1;" : "=r"(r) : "f"(f));
    return r;
}
__device__ __forceinline__ float rna_tf32(float f) { return __uint_as_float(rna_tf32_u(f)); }

__device__ __forceinline__ void cp_async16(uint32_t dst, const void* src) {
    asm volatile("cp.async.cg.shared.global [%0], [%1], 16;" :: "r"(dst), "l"(src));
}
#define CP_COMMIT()  asm volatile("cp.async.commit_group;" ::: "memory")
#define CP_WAIT(n)   asm volatile("cp.async.wait_group %0;" :: "n"(n) : "memory")

__device__ __forceinline__ void mma_tf32(float* c, const uint32_t* a, uint32_t b0, uint32_t b1) {
    asm volatile(
        "mma.sync.aligned.m16n8k8.row.col.f32.tf32.tf32.f32 "
        "{%0,%1,%2,%3}, {%4,%5,%6,%7}, {%8,%9}, {%0,%1,%2,%3};"
        : "+f"(c[0]), "+f"(c[1]), "+f"(c[2]), "+f"(c[3])
        : "r"(a[0]), "r"(a[1]), "r"(a[2]), "r"(a[3]), "r"(b0), "r"(b1));
}

// ===================== W fragment image =====================
// Per (ch, kc): 4096-float image; per warp-half h, ntpair p, kstep ks the float4 at
// [h*512 + p*128 + ks*32 + lane] = { W[c0][k], W[c0][k+4], W[c0+8][k], W[c0+8][k+4] },
// c0 = 64h + 16p + (lane>>2), k = kc*32 + ks*8 + (lane&3).
__device__ __align__(16) float g_Wimg[8 * K_DIM * N_DIM];

__global__ void prep_w_kernel(const float* __restrict__ W) {
    int idx = blockIdx.x * blockDim.x + threadIdx.x;   // 0 .. 131071
    if (idx >= 8 * 128 * 128) return;
    int ch = idx >> 14;
    int n  = (idx >> 7) & 127;
    int k  = idx & 127;
    int h = n >> 6, colh = n & 63;
    int p = colh >> 4, ntodd = (colh >> 3) & 1, cs = colh & 7;
    int kc = k >> 5, kk = k & 31;
    int ks = kk >> 3, klo = kk & 3, khi = (kk >> 2) & 1;
    int fi = (((h * 4 + p) * 4 + ks) * 8 + cs) * 16 + klo * 4 + ntodd * 2 + khi;
    g_Wimg[(ch * 4 + kc) * SW_FLOATS + fi] = rna_tf32(W[idx]);
}

// ===================== stage loader =====================
__device__ __forceinline__ void load_stage(uint32_t sm_base, int stage,
                                           const float* __restrict__ x,
                                           int job, int kc, int tid) {
    const float* a_base = x + (size_t)job * (ROWS_CTA * K_DIM);
    const int ch = (job >> 1) & 7;
    const float* wsrc = g_Wimg + (ch * 4 + kc) * SW_FLOATS;

    uint32_t sa = sm_base + (uint32_t)(stage * STAGE_FLOATS) * 4u;
    uint32_t sw = sa + SA_FLOATS * 4u;
#pragma unroll
    for (int j = 0; j < 4; j++) {
        int pid = j * THREADS + tid;          // 0..1023 16B pieces of A
        int r = pid >> 3, pc = pid & 7;
        cp_async16(sa + (uint32_t)(r * SA_STRIDE + pc * 4) * 4u,
                   a_base + r * K_DIM + kc * K_CHUNK + pc * 4);
    }
#pragma unroll
    for (int j = 0; j < 4; j++) {
        int pid = j * THREADS + tid;          // 16KB W image verbatim
        cp_async16(sw + (uint32_t)pid * 16u, wsrc + pid * 4);
    }
    CP_COMMIT();
}

// ===================== main GEMM (persistent CTAs) =====================
__global__ __launch_bounds__(THREADS, 2)
void gemm_kernel(const float* __restrict__ x, const float* __restrict__ bias,
                 float* __restrict__ out) {
    extern __shared__ __align__(16) float smem[];
    const uint32_t sm_base = smem_u32(smem);

    const int tid  = threadIdx.x;
    const int lane = tid & 31;
    const int wid  = tid >> 5;

    // all-channel bias staged once
    {
        float4 v = *(const float4*)(bias + tid * 4);
        *(float4*)(smem + SM_BIAS_OFF + tid * 4) = v;
    }

    const int warpM = (wid >> 1) * 32;
    const int h     = (wid & 1);
    const int aoff  = (warpM + (lane >> 2)) * SA_STRIDE + (lane & 3);

    // prologue: first two chunks of first job
    const int job0 = blockIdx.x;
    load_stage(sm_base, 0, x, job0, 0, tid);
    load_stage(sm_base, 1, x, job0, 1, tid);

    int s = 0;   // stage of the chunk about to be computed

    for (int job = job0; job < NUM_JOBS; job += GRID) {
        float acc[2][8][4];
#pragma unroll
        for (int mt = 0; mt < 2; mt++)
#pragma unroll
            for (int nt = 0; nt < 8; nt++)
#pragma unroll
                for (int q = 0; q < 4; q++) acc[mt][nt][q] = 0.0f;

#pragma unroll
        for (int kc = 0; kc < NCHUNK; kc++) {
            // chunk t+2 coordinates (may roll into next job)
            const int jobN = (kc < 2) ? job : job + GRID;
            const int kcN  = (kc + 2) & 3;
            const bool have = (jobN < NUM_JOBS);

            if (have) { CP_WAIT(1); } else { CP_WAIT(0); }
            __syncthreads();
            if (have) {
                int sN = s + 2; if (sN >= STAGES) sN -= STAGES;
                load_stage(sm_base, sN, x, jobN, kcN, tid);
            }

            const float* sa = smem + s * STAGE_FLOATS;
            const float4* bW = (const float4*)(sa + SA_FLOATS) + h * 512 + lane;
            const float* aF = sa + aoff;

#pragma unroll
            for (int ks = 0; ks < 4; ks++) {
                uint32_t afr[2][4];
#pragma unroll
                for (int mt = 0; mt < 2; mt++) {
                    const float* ap = aF + mt * 16 * SA_STRIDE + ks * 8;
                    afr[mt][0] = rna_tf32_u(ap[0]);
                    afr[mt][1] = rna_tf32_u(ap[8 * SA_STRIDE]);
                    afr[mt][2] = rna_tf32_u(ap[4]);
                    afr[mt][3] = rna_tf32_u(ap[8 * SA_STRIDE + 4]);
                }
#pragma unroll
                for (int p = 0; p < 4; p++) {
                    float4 f = bW[p * 128 + ks * 32];
                    uint32_t b0x = __float_as_uint(f.x), b0y = __float_as_uint(f.y);
                    uint32_t b1x = __float_as_uint(f.z), b1y = __float_as_uint(f.w);
                    mma_tf32(acc[0][2 * p],     afr[0], b0x, b0y);
                    mma_tf32(acc[0][2 * p + 1], afr[0], b1x, b1y);
                    mma_tf32(acc[1][2 * p],     afr[1], b0x, b0y);
                    mma_tf32(acc[1][2 * p + 1], afr[1], b1x, b1y);
                }
            }
            s++; if (s >= STAGES) s -= STAGES;
        }

        // ---- epilogue: overlaps with next job's in-flight loads ----
        {
            float* o_base = out + (size_t)job * (ROWS_CTA * N_DIM);
            const float* sB = smem + SM_BIAS_OFF + ((job >> 1) & 7) * 128;
            const int r0 = warpM + (lane >> 2);
            const int n0 = h * 64 + (lane & 3) * 2;
#pragma unroll
            for (int mt = 0; mt < 2; mt++) {
#pragma unroll
                for (int hh = 0; hh < 2; hh++) {
                    int row = r0 + mt * 16 + hh * 8;
                    float* orow = o_base + (size_t)row * N_DIM;
#pragma unroll
                    for (int nt = 0; nt < 8; nt++) {
                        int n = n0 + nt * 8;
                        float2 v;
                        v.x = acc[mt][nt][hh * 2 + 0] + sB[n];
                        v.y = acc[mt][nt][hh * 2 + 1] + sB[n + 1];
                        *(float2*)(orow + n) = v;
                    }
                }
            }
        }
    }
}

// ===================== launch =====================
extern "C" void kernel_launch(void* const* d_in, const int* in_sizes, int n_in,
                              void* d_out, int out_size) {
    const float* x = (const float*)d_in[0];
    const float* W = (const float*)d_in[1];
    const float* b = (const float*)d_in[2];
    float* out = (float*)d_out;

    cudaFuncSetAttribute(gemm_kernel, cudaFuncAttributeMaxDynamicSharedMemorySize, SMEM_BYTES);

    prep_w_kernel<<<512, 256>>>(W);
    gemm_kernel<<<GRID, THREADS, SMEM_BYTES>>>(x, b, out);
}

// round 5
// speedup vs baseline: 1.0256x; 1.0256x over previous
#include <cuda_runtime.h>
#include <cuda_bf16.h>
#include <cstdint>

// ===================== problem constants =====================
// x: 262144 rows x 128 (row = (b,i,r,p,g)); W: (8,128,128); b: (8,128)
// CTA job: 128 rows (M) x 128 cols (N) x K=128. Channel constant per 2 jobs.
#define N_DIM      128
#define K_DIM      128
#define ROWS_CTA   128
#define THREADS    512
#define NUM_CTAS   2048
#define K_CHUNK    32
#define NCHUNK     4
#define STAGES     3

// ---- smem layout (floats) ----
#define SA_STRIDE  36                          // 36 mod 32 == 4 -> conflict-free frag reads
#define SA_FLOATS  (128 * SA_STRIDE)           // 4608
#define SW_FLOATS  4096                        // W chunk fragment image: 128 x 32
#define STAGE_FLOATS (SA_FLOATS + SW_FLOATS)   // 8704
#define SM_BIAS_OFF  (STAGES * STAGE_FLOATS)   // 26112
#define SMEM_FLOATS  (SM_BIAS_OFF + 128)
#define SMEM_BYTES   (SMEM_FLOATS * 4)         // 104,960 (x2 CTAs = 210KB <= 228KB)

// ===================== helpers =====================
__device__ __forceinline__ uint32_t smem_u32(const void* p) {
    uint32_t a;
    asm("{ .reg .u64 t; cvta.to.shared.u64 t, %1; cvt.u32.u64 %0, t; }" : "=r"(a) : "l"(p));
    return a;
}
__device__ __forceinline__ uint32_t rna_tf32_u(float f) {
    uint32_t r;
    asm("cvt.rna.tf32.f32 %0, %1;" : "=r"(r) : "f"(f));
    return r;
}
__device__ __forceinline__ float rna_tf32(float f) { return __uint_as_float(rna_tf32_u(f)); }

__device__ __forceinline__ void cp_async16(uint32_t dst, const void* src) {
    asm volatile("cp.async.cg.shared.global [%0], [%1], 16;" :: "r"(dst), "l"(src));
}
#define CP_COMMIT()  asm volatile("cp.async.commit_group;" ::: "memory")
#define CP_WAIT(n)   asm volatile("cp.async.wait_group %0;" :: "n"(n) : "memory")

__device__ __forceinline__ void mma_tf32(float* c, const uint32_t* a, uint32_t b0, uint32_t b1) {
    asm volatile(
        "mma.sync.aligned.m16n8k8.row.col.f32.tf32.tf32.f32 "
        "{%0,%1,%2,%3}, {%4,%5,%6,%7}, {%8,%9}, {%0,%1,%2,%3};"
        : "+f"(c[0]), "+f"(c[1]), "+f"(c[2]), "+f"(c[3])
        : "r"(a[0]), "r"(a[1]), "r"(a[2]), "r"(a[3]), "r"(b0), "r"(b1));
}

// ===================== W fragment image =====================
// Per (ch, kc): 4096-float image. For 16-col group g16 (0..7), kstep ks, the float4 at
// f4-index [g16*128 + ks*32 + lane] = { W[c0][k], W[c0][k+4], W[c0+8][k], W[c0+8][k+4] },
// c0 = 16*g16 + (lane>>2), k = kc*32 + ks*8 + (lane&3).
__device__ __align__(16) float g_Wimg[8 * K_DIM * N_DIM];

__global__ void prep_w_kernel(const float* __restrict__ W) {
    int idx = blockIdx.x * blockDim.x + threadIdx.x;   // 0 .. 131071
    if (idx >= 8 * 128 * 128) return;
    int ch = idx >> 14;
    int n  = (idx >> 7) & 127;
    int k  = idx & 127;
    int g16 = n >> 4, col = n & 15;
    int ntodd = (col >> 3) & 1, cs = col & 7;
    int kc = k >> 5, kk = k & 31;
    int ks = kk >> 3, klo = kk & 3, khi = (kk >> 2) & 1;
    int fi = ((g16 * 4 + ks) * 8 + cs) * 16 + klo * 4 + ntodd * 2 + khi;
    g_Wimg[(ch * 4 + kc) * SW_FLOATS + fi] = rna_tf32(W[idx]);
}

// ===================== stage loader (512 threads) =====================
__device__ __forceinline__ void load_stage(uint32_t sm_base, int stage,
                                           const float* a_base, const float* wimg_ch,
                                           int kc, int tid) {
    uint32_t sa = sm_base + (uint32_t)(stage * STAGE_FLOATS) * 4u;
    uint32_t sw = sa + SA_FLOATS * 4u;
    // A chunk: 128 rows x 32 floats = 1024 x 16B pieces
#pragma unroll
    for (int j = 0; j < 2; j++) {
        int pid = j * THREADS + tid;
        int r = pid >> 3, pc = pid & 7;
        cp_async16(sa + (uint32_t)(r * SA_STRIDE + pc * 4) * 4u,
                   a_base + r * K_DIM + kc * K_CHUNK + pc * 4);
    }
    // W chunk image: verbatim 16KB
    const float* wsrc = wimg_ch + kc * SW_FLOATS;
#pragma unroll
    for (int j = 0; j < 2; j++) {
        int pid = j * THREADS + tid;
        cp_async16(sw + (uint32_t)pid * 16u, wsrc + pid * 4);
    }
    CP_COMMIT();
}

// ===================== main GEMM =====================
__global__ __launch_bounds__(THREADS, 2)
void gemm_kernel(const float* __restrict__ x, const float* __restrict__ bias,
                 float* __restrict__ out) {
    extern __shared__ __align__(16) float smem[];
    const uint32_t sm_base = smem_u32(smem);

    const int tid  = threadIdx.x;
    const int lane = tid & 31;
    const int wid  = tid >> 5;
    const int blk  = blockIdx.x;
    const int ch   = (blk >> 1) & 7;

    const float* a_base  = x + (size_t)blk * (ROWS_CTA * K_DIM);
    float*       o_base  = out + (size_t)blk * (ROWS_CTA * N_DIM);
    const float* wimg_ch = g_Wimg + ch * (K_DIM * N_DIM);

    if (tid < 128) smem[SM_BIAS_OFF + tid] = bias[ch * 128 + tid];

    // 16 warps: 4 over M (32 rows each) x 4 over N (32 cols each)
    const int wm = wid >> 2;          // 0..3
    const int wn = wid & 3;           // 0..3

    float acc[2][4][4];
#pragma unroll
    for (int mt = 0; mt < 2; mt++)
#pragma unroll
        for (int nt = 0; nt < 4; nt++)
#pragma unroll
            for (int q = 0; q < 4; q++) acc[mt][nt][q] = 0.0f;

    // prologue: prefetch stages 0,1
    load_stage(sm_base, 0, a_base, wimg_ch, 0, tid);
    load_stage(sm_base, 1, a_base, wimg_ch, 1, tid);

    const int aoff = (wm * 32 + (lane >> 2)) * SA_STRIDE + (lane & 3);
    const int boff = wn * 2 * 128 + lane;        // float4 index base for this warp's cols

#pragma unroll
    for (int kc = 0; kc < NCHUNK; kc++) {
        if (kc < NCHUNK - 1) { CP_WAIT(1); } else { CP_WAIT(0); }
        __syncthreads();
        if (kc + 2 < NCHUNK)
            load_stage(sm_base, (kc + 2) % STAGES, a_base, wimg_ch, kc + 2, tid);

        const float* sa = smem + (kc % STAGES) * STAGE_FLOATS;
        const float4* bW = (const float4*)(sa + SA_FLOATS) + boff;
        const float* aF = sa + aoff;

#pragma unroll
        for (int ks = 0; ks < 4; ks++) {
            uint32_t afr[2][4];
#pragma unroll
            for (int mt = 0; mt < 2; mt++) {
                const float* ap = aF + mt * 16 * SA_STRIDE + ks * 8;
                afr[mt][0] = rna_tf32_u(ap[0]);
                afr[mt][1] = rna_tf32_u(ap[8 * SA_STRIDE]);
                afr[mt][2] = rna_tf32_u(ap[4]);
                afr[mt][3] = rna_tf32_u(ap[8 * SA_STRIDE + 4]);
            }
#pragma unroll
            for (int p = 0; p < 2; p++) {
                float4 f = bW[p * 128 + ks * 32];
                uint32_t b0x = __float_as_uint(f.x), b0y = __float_as_uint(f.y);
                uint32_t b1x = __float_as_uint(f.z), b1y = __float_as_uint(f.w);
                mma_tf32(acc[0][2 * p],     afr[0], b0x, b0y);
                mma_tf32(acc[0][2 * p + 1], afr[0], b1x, b1y);
                mma_tf32(acc[1][2 * p],     afr[1], b0x, b0y);
                mma_tf32(acc[1][2 * p + 1], afr[1], b1x, b1y);
            }
        }
    }

    // ---- epilogue: accum + bias -> gmem (float2, full sectors across warps) ----
    const float* sB = smem + SM_BIAS_OFF;
    const int r0 = wm * 32 + (lane >> 2);
    const int n0 = wn * 32 + (lane & 3) * 2;
#pragma unroll
    for (int mt = 0; mt < 2; mt++) {
#pragma unroll
        for (int hh = 0; hh < 2; hh++) {
            int row = r0 + mt * 16 + hh * 8;
            float* orow = o_base + (size_t)row * N_DIM;
#pragma unroll
            for (int nt = 0; nt < 4; nt++) {
                int n = n0 + nt * 8;
                float2 v;
                v.x = acc[mt][nt][hh * 2 + 0] + sB[n];
                v.y = acc[mt][nt][hh * 2 + 1] + sB[n + 1];
                *(float2*)(orow + n) = v;
            }
        }
    }
}

// ===================== launch =====================
extern "C" void kernel_launch(void* const* d_in, const int* in_sizes, int n_in,
                              void* d_out, int out_size) {
    const float* x = (const float*)d_in[0];
    const float* W = (const float*)d_in[1];
    const float* b = (const float*)d_in[2];
    float* out = (float*)d_out;

    cudaFuncSetAttribute(gemm_kernel, cudaFuncAttributeMaxDynamicSharedMemorySize, SMEM_BYTES);

    prep_w_kernel<<<512, 256>>>(W);
    gemm_kernel<<<NUM_CTAS, THREADS, SMEM_BYTES>>>(x, b, out);
}

// round 6
// speedup vs baseline: 1.0811x; 1.0541x over previous
#include <cuda_runtime.h>
#include <cuda_bf16.h>
#include <cstdint>

// ===================== problem constants =====================
// x: 262144 rows x 128 (row = (b,i,r,p,g)); W: (8,128,128); b: (8,128)
// CTA job: 128 rows (M) x 128 cols (N) x K=128. Channel constant per 2 jobs.
#define N_DIM      128
#define K_DIM      128
#define ROWS_CTA   128
#define THREADS    512
#define NUM_CTAS   2048
#define K_CHUNK    32
#define NCHUNK     4
#define STAGES     3

// ---- smem layout (floats) ----
#define SA_STRIDE  36                          // 36 mod 32 == 4 -> conflict-free LDSM phases
#define SA_FLOATS  (128 * SA_STRIDE)           // 4608
#define SW_FLOATS  4096                        // W chunk fragment image: 128 x 32
#define STAGE_FLOATS (SA_FLOATS + SW_FLOATS)   // 8704
#define SM_BIAS_OFF  (STAGES * STAGE_FLOATS)   // 26112
#define SMEM_FLOATS  (SM_BIAS_OFF + 128)
#define SMEM_BYTES   (SMEM_FLOATS * 4)         // 104,960 (x2 CTAs = 210KB <= 228KB)

// ===================== helpers =====================
__device__ __forceinline__ uint32_t smem_u32(const void* p) {
    uint32_t a;
    asm("{ .reg .u64 t; cvta.to.shared.u64 t, %1; cvt.u32.u64 %0, t; }" : "=r"(a) : "l"(p));
    return a;
}
__device__ __forceinline__ uint32_t rna_tf32_u(float f) {
    uint32_t r;
    asm("cvt.rna.tf32.f32 %0, %1;" : "=r"(r) : "f"(f));
    return r;
}
__device__ __forceinline__ float rna_tf32(float f) { return __uint_as_float(rna_tf32_u(f)); }

__device__ __forceinline__ void cp_async16(uint32_t dst, const void* src) {
    asm volatile("cp.async.cg.shared.global [%0], [%1], 16;" :: "r"(dst), "l"(src));
}
#define CP_COMMIT()  asm volatile("cp.async.commit_group;" ::: "memory")
#define CP_WAIT(n)   asm volatile("cp.async.wait_group %0;" :: "n"(n) : "memory")

// ldmatrix x4: one tf32 8x4 block == one 8x8 b16 tile; returns raw fp32 bits
__device__ __forceinline__ void ldsm_x4(uint32_t& r0, uint32_t& r1, uint32_t& r2, uint32_t& r3,
                                        uint32_t addr) {
    asm volatile("ldmatrix.sync.aligned.m8n8.x4.shared.b16 {%0,%1,%2,%3}, [%4];"
                 : "=r"(r0), "=r"(r1), "=r"(r2), "=r"(r3) : "r"(addr));
}

__device__ __forceinline__ void mma_tf32(float* c, const uint32_t* a, uint32_t b0, uint32_t b1) {
    asm volatile(
        "mma.sync.aligned.m16n8k8.row.col.f32.tf32.tf32.f32 "
        "{%0,%1,%2,%3}, {%4,%5,%6,%7}, {%8,%9}, {%0,%1,%2,%3};"
        : "+f"(c[0]), "+f"(c[1]), "+f"(c[2]), "+f"(c[3])
        : "r"(a[0]), "r"(a[1]), "r"(a[2]), "r"(a[3]), "r"(b0), "r"(b1));
}

// ===================== W fragment image =====================
// Per (ch, kc): 4096-float image. For 16-col group g16 (0..7), kstep ks, the float4 at
// f4-index [g16*128 + ks*32 + lane] = { W[c0][k], W[c0][k+4], W[c0+8][k], W[c0+8][k+4] },
// c0 = 16*g16 + (lane>>2), k = kc*32 + ks*8 + (lane&3).
__device__ __align__(16) float g_Wimg[8 * K_DIM * N_DIM];

__global__ void prep_w_kernel(const float* __restrict__ W) {
    int idx = blockIdx.x * blockDim.x + threadIdx.x;   // 0 .. 131071
    if (idx >= 8 * 128 * 128) return;
    int ch = idx >> 14;
    int n  = (idx >> 7) & 127;
    int k  = idx & 127;
    int g16 = n >> 4, col = n & 15;
    int ntodd = (col >> 3) & 1, cs = col & 7;
    int kc = k >> 5, kk = k & 31;
    int ks = kk >> 3, klo = kk & 3, khi = (kk >> 2) & 1;
    int fi = ((g16 * 4 + ks) * 8 + cs) * 16 + klo * 4 + ntodd * 2 + khi;
    g_Wimg[(ch * 4 + kc) * SW_FLOATS + fi] = rna_tf32(W[idx]);
}

// ===================== stage loader (512 threads) =====================
__device__ __forceinline__ void load_stage(uint32_t sm_base, int stage,
                                           const float* a_base, const float* wimg_ch,
                                           int kc, int tid) {
    uint32_t sa = sm_base + (uint32_t)(stage * STAGE_FLOATS) * 4u;
    uint32_t sw = sa + SA_FLOATS * 4u;
    // A chunk: 128 rows x 32 floats = 1024 x 16B pieces
#pragma unroll
    for (int j = 0; j < 2; j++) {
        int pid = j * THREADS + tid;
        int r = pid >> 3, pc = pid & 7;
        cp_async16(sa + (uint32_t)(r * SA_STRIDE + pc * 4) * 4u,
                   a_base + r * K_DIM + kc * K_CHUNK + pc * 4);
    }
    // W chunk image: verbatim 16KB
    const float* wsrc = wimg_ch + kc * SW_FLOATS;
#pragma unroll
    for (int j = 0; j < 2; j++) {
        int pid = j * THREADS + tid;
        cp_async16(sw + (uint32_t)pid * 16u, wsrc + pid * 4);
    }
    CP_COMMIT();
}

// ===================== main GEMM =====================
__global__ __launch_bounds__(THREADS, 2)
void gemm_kernel(const float* __restrict__ x, const float* __restrict__ bias,
                 float* __restrict__ out) {
    extern __shared__ __align__(16) float smem[];
    const uint32_t sm_base = smem_u32(smem);

    const int tid  = threadIdx.x;
    const int lane = tid & 31;
    const int wid  = tid >> 5;
    const int blk  = blockIdx.x;
    const int ch   = (blk >> 1) & 7;

    const float* a_base  = x + (size_t)blk * (ROWS_CTA * K_DIM);
    float*       o_base  = out + (size_t)blk * (ROWS_CTA * N_DIM);
    const float* wimg_ch = g_Wimg + ch * (K_DIM * N_DIM);

    if (tid < 128) smem[SM_BIAS_OFF + tid] = bias[ch * 128 + tid];

    // 16 warps: 4 over M (32 rows each) x 4 over N (32 cols each)
    const int wm = wid >> 2;          // 0..3
    const int wn = wid & 3;           // 0..3

    float acc[2][4][4];
#pragma unroll
    for (int mt = 0; mt < 2; mt++)
#pragma unroll
        for (int nt = 0; nt < 4; nt++)
#pragma unroll
            for (int q = 0; q < 4; q++) acc[mt][nt][q] = 0.0f;

    // prologue: prefetch stages 0,1
    load_stage(sm_base, 0, a_base, wimg_ch, 0, tid);
    load_stage(sm_base, 1, a_base, wimg_ch, 1, tid);

    // LDSM per-lane address: lanes 0-7 rows m..m+7 @k0; 8-15 rows m+8..m+15 @k0;
    // 16-23 rows m..m+7 @k0+4; 24-31 rows m+8..m+15 @k0+4.
    const uint32_t a_lds_base = sm_base +
        (uint32_t)(((wm * 32 + (lane & 15)) * SA_STRIDE + (lane >> 4) * 4) * 4);
    const int boff = wn * 2 * 128 + lane;        // float4 index base for this warp's cols

#pragma unroll
    for (int kc = 0; kc < NCHUNK; kc++) {
        if (kc < NCHUNK - 1) { CP_WAIT(1); } else { CP_WAIT(0); }
        __syncthreads();
        if (kc + 2 < NCHUNK)
            load_stage(sm_base, (kc + 2) % STAGES, a_base, wimg_ch, kc + 2, tid);

        const uint32_t stage_b = (uint32_t)((kc % STAGES) * STAGE_FLOATS) * 4u;
        const float* sa = smem + (kc % STAGES) * STAGE_FLOATS;
        const float4* bW = (const float4*)(sa + SA_FLOATS) + boff;
        const uint32_t aL = a_lds_base + stage_b;

#pragma unroll
        for (int ks = 0; ks < 4; ks++) {
            uint32_t afr[2][4];
#pragma unroll
            for (int mt = 0; mt < 2; mt++) {
                uint32_t r0, r1, r2, r3;
                ldsm_x4(r0, r1, r2, r3, aL + (uint32_t)(mt * 16 * SA_STRIDE * 4 + ks * 32));
                afr[mt][0] = rna_tf32_u(__uint_as_float(r0));
                afr[mt][1] = rna_tf32_u(__uint_as_float(r1));
                afr[mt][2] = rna_tf32_u(__uint_as_float(r2));
                afr[mt][3] = rna_tf32_u(__uint_as_float(r3));
            }
#pragma unroll
            for (int p = 0; p < 2; p++) {
                float4 f = bW[p * 128 + ks * 32];
                uint32_t b0x = __float_as_uint(f.x), b0y = __float_as_uint(f.y);
                uint32_t b1x = __float_as_uint(f.z), b1y = __float_as_uint(f.w);
                mma_tf32(acc[0][2 * p],     afr[0], b0x, b0y);
                mma_tf32(acc[0][2 * p + 1], afr[0], b1x, b1y);
                mma_tf32(acc[1][2 * p],     afr[1], b0x, b0y);
                mma_tf32(acc[1][2 * p + 1], afr[1], b1x, b1y);
            }
        }
    }

    // ---- epilogue: accum + bias -> gmem (float2, full sectors across warps) ----
    const float* sB = smem + SM_BIAS_OFF;
    const int r0 = wm * 32 + (lane >> 2);
    const int n0 = wn * 32 + (lane & 3) * 2;
#pragma unroll
    for (int mt = 0; mt < 2; mt++) {
#pragma unroll
        for (int hh = 0; hh < 2; hh++) {
            int row = r0 + mt * 16 + hh * 8;
            float* orow = o_base + (size_t)row * N_DIM;
#pragma unroll
            for (int nt = 0; nt < 4; nt++) {
                int n = n0 + nt * 8;
                float2 v;
                v.x = acc[mt][nt][hh * 2 + 0] + sB[n];
                v.y = acc[mt][nt][hh * 2 + 1] + sB[n + 1];
                *(float2*)(orow + n) = v;
            }
        }
    }
}

// ===================== launch =====================
extern "C" void kernel_launch(void* const* d_in, const int* in_sizes, int n_in,
                              void* d_out, int out_size) {
    const float* x = (const float*)d_in[0];
    const float* W = (const float*)d_in[1];
    const float* b = (const float*)d_in[2];
    float* out = (float*)d_out;

    cudaFuncSetAttribute(gemm_kernel, cudaFuncAttributeMaxDynamicSharedMemorySize, SMEM_BYTES);

    prep_w_kernel<<<512, 256>>>(W);
    gemm_kernel<<<NUM_CTAS, THREADS, SMEM_BYTES>>>(x, b, out);
}

// round 7
// speedup vs baseline: 1.1312x; 1.0463x over previous
#include <cuda_runtime.h>
#include <cuda_bf16.h>
#include <cstdint>

// ===================== problem constants =====================
// x: 262144 rows x 128; W: (8,128,128); b: (8,128)
// CTA job: 128 rows (M) x 128 cols (N) x K=128. Channel constant per 2 jobs.
#define N_DIM      128
#define K_DIM      128
#define ROWS_CTA   128
#define THREADS    256
#define NUM_CTAS   2048
#define K_CHUNK    32
#define NCHUNK     4
#define STAGES     3

// ---- smem layout (floats) ----
#define SA_STRIDE  36                          // 36 mod 32 == 4 -> conflict-free LDSM phases
#define SA_FLOATS  (128 * SA_STRIDE)           // 4608
#define SW_FLOATS  4096                        // W chunk fragment image: 128 x 32
#define STAGE_FLOATS (SA_FLOATS + SW_FLOATS)   // 8704
#define SM_BIAS_OFF  (STAGES * STAGE_FLOATS)   // 26112
#define SMEM_FLOATS  (SM_BIAS_OFF + 128)
#define SMEM_BYTES   (SMEM_FLOATS * 4)         // 104,960 (x2 CTAs = 210KB <= 228KB)

// ===================== helpers =====================
__device__ __forceinline__ uint32_t smem_u32(const void* p) {
    uint32_t a;
    asm("{ .reg .u64 t; cvta.to.shared.u64 t, %1; cvt.u32.u64 %0, t; }" : "=r"(a) : "l"(p));
    return a;
}
__device__ __forceinline__ uint32_t rna_tf32_u(float f) {
    uint32_t r;
    asm("cvt.rna.tf32.f32 %0, %1;" : "=r"(r) : "f"(f));
    return r;
}
__device__ __forceinline__ float rna_tf32(float f) { return __uint_as_float(rna_tf32_u(f)); }

__device__ __forceinline__ void cp_async16(uint32_t dst, const void* src) {
    asm volatile("cp.async.cg.shared.global [%0], [%1], 16;" :: "r"(dst), "l"(src));
}
#define CP_COMMIT()  asm volatile("cp.async.commit_group;" ::: "memory")
#define CP_WAIT(n)   asm volatile("cp.async.wait_group %0;" :: "n"(n) : "memory")

// ldmatrix x4: one tf32 8x4 block == one 8x8 b16 tile; returns raw fp32 bits
__device__ __forceinline__ void ldsm_x4(uint32_t& r0, uint32_t& r1, uint32_t& r2, uint32_t& r3,
                                        uint32_t addr) {
    asm volatile("ldmatrix.sync.aligned.m8n8.x4.shared.b16 {%0,%1,%2,%3}, [%4];"
                 : "=r"(r0), "=r"(r1), "=r"(r2), "=r"(r3) : "r"(addr));
}

__device__ __forceinline__ void mma_tf32(float* c, const uint32_t* a, uint32_t b0, uint32_t b1) {
    asm volatile(
        "mma.sync.aligned.m16n8k8.row.col.f32.tf32.tf32.f32 "
        "{%0,%1,%2,%3}, {%4,%5,%6,%7}, {%8,%9}, {%0,%1,%2,%3};"
        : "+f"(c[0]), "+f"(c[1]), "+f"(c[2]), "+f"(c[3])
        : "r"(a[0]), "r"(a[1]), "r"(a[2]), "r"(a[3]), "r"(b0), "r"(b1));
}

// ===================== W fragment image =====================
// Per (ch, kc): 4096-float image. For warp half h (warpN=64h), ntpair p, kstep ks:
// float4 at [h*512 + p*128 + ks*32 + lane] = { W[c0][k], W[c0][k+4], W[c0+8][k], W[c0+8][k+4] },
// c0 = 64h + 16p + (lane>>2), k = kc*32 + ks*8 + (lane&3).
__device__ __align__(16) float g_Wimg[8 * K_DIM * N_DIM];

__global__ void prep_w_kernel(const float* __restrict__ W) {
    int idx = blockIdx.x * blockDim.x + threadIdx.x;   // 0 .. 131071
    if (idx >= 8 * 128 * 128) return;
    int ch = idx >> 14;
    int n  = (idx >> 7) & 127;
    int k  = idx & 127;
    int h = n >> 6, colh = n & 63;
    int p = colh >> 4, ntodd = (colh >> 3) & 1, cs = colh & 7;
    int kc = k >> 5, kk = k & 31;
    int ks = kk >> 3, klo = kk & 3, khi = (kk >> 2) & 1;
    int fi = (((h * 4 + p) * 4 + ks) * 8 + cs) * 16 + klo * 4 + ntodd * 2 + khi;
    g_Wimg[(ch * 4 + kc) * SW_FLOATS + fi] = rna_tf32(W[idx]);
}

// ===================== stage loader (256 threads) =====================
__device__ __forceinline__ void load_stage(uint32_t sm_base, int stage,
                                           const float* a_base, const float* wimg_ch,
                                           int kc, int tid) {
    uint32_t sa = sm_base + (uint32_t)(stage * STAGE_FLOATS) * 4u;
    uint32_t sw = sa + SA_FLOATS * 4u;
#pragma unroll
    for (int j = 0; j < 4; j++) {
        int pid = j * THREADS + tid;          // 0..1023 16B pieces of A
        int r = pid >> 3, pc = pid & 7;
        cp_async16(sa + (uint32_t)(r * SA_STRIDE + pc * 4) * 4u,
                   a_base + r * K_DIM + kc * K_CHUNK + pc * 4);
    }
    const float* wsrc = wimg_ch + kc * SW_FLOATS;
#pragma unroll
    for (int j = 0; j < 4; j++) {
        int pid = j * THREADS + tid;          // 16KB W image verbatim
        cp_async16(sw + (uint32_t)pid * 16u, wsrc + pid * 4);
    }
    CP_COMMIT();
}

// ===================== main GEMM =====================
__global__ __launch_bounds__(THREADS, 2)
void gemm_kernel(const float* __restrict__ x, const float* __restrict__ bias,
                 float* __restrict__ out) {
    extern __shared__ __align__(16) float smem[];
    const uint32_t sm_base = smem_u32(smem);

    const int tid  = threadIdx.x;
    const int lane = tid & 31;
    const int wid  = tid >> 5;
    const int blk  = blockIdx.x;
    const int ch   = (blk >> 1) & 7;

    const float* a_base  = x + (size_t)blk * (ROWS_CTA * K_DIM);
    float*       o_base  = out + (size_t)blk * (ROWS_CTA * N_DIM);
    const float* wimg_ch = g_Wimg + ch * (K_DIM * N_DIM);

    if (tid < 128) smem[SM_BIAS_OFF + tid] = bias[ch * 128 + tid];

    // 8 warps: 4 over M (32 rows each), 2 over N (64 cols each)
    const int warpM = (wid >> 1) * 32;
    const int h     = (wid & 1);

    float acc[2][8][4];
#pragma unroll
    for (int mt = 0; mt < 2; mt++)
#pragma unroll
        for (int nt = 0; nt < 8; nt++)
#pragma unroll
            for (int q = 0; q < 4; q++) acc[mt][nt][q] = 0.0f;

    // prologue: prefetch stages 0,1
    load_stage(sm_base, 0, a_base, wimg_ch, 0, tid);
    load_stage(sm_base, 1, a_base, wimg_ch, 1, tid);

    // LDSM lane address: lanes 0-15 -> rows warpM+(lane&15) @ k0; lanes 16-31 -> same rows @ k0+4
    const uint32_t a_lds_base = sm_base +
        (uint32_t)(((warpM + (lane & 15)) * SA_STRIDE + (lane >> 4) * 4) * 4);
    const int boff = h * 512 + lane;          // float4 index base for this warp's cols

#pragma unroll
    for (int kc = 0; kc < NCHUNK; kc++) {
        if (kc < NCHUNK - 1) { CP_WAIT(1); } else { CP_WAIT(0); }
        __syncthreads();
        if (kc + 2 < NCHUNK)
            load_stage(sm_base, (kc + 2) % STAGES, a_base, wimg_ch, kc + 2, tid);

        const float* sa = smem + (kc % STAGES) * STAGE_FLOATS;
        const float4* bW = (const float4*)(sa + SA_FLOATS) + boff;
        const uint32_t aL = a_lds_base + (uint32_t)((kc % STAGES) * STAGE_FLOATS) * 4u;

        // A-fragment ping-pong buffers (cur = buf[ks&1])
        uint32_t afr[2][2][4];

        // preload ks=0 fragments
#pragma unroll
        for (int mt = 0; mt < 2; mt++) {
            uint32_t r0, r1, r2, r3;
            ldsm_x4(r0, r1, r2, r3, aL + (uint32_t)(mt * 16 * SA_STRIDE * 4));
            afr[0][mt][0] = rna_tf32_u(__uint_as_float(r0));
            afr[0][mt][1] = rna_tf32_u(__uint_as_float(r1));
            afr[0][mt][2] = rna_tf32_u(__uint_as_float(r2));
            afr[0][mt][3] = rna_tf32_u(__uint_as_float(r3));
        }

#pragma unroll
        for (int ks = 0; ks < 4; ks++) {
            const int cur = ks & 1, nxt = cur ^ 1;

            // B fragments for this ks (4 independent LDS.128, covered by MMA stream)
            float4 f0 = bW[0 * 128 + ks * 32];
            float4 f1 = bW[1 * 128 + ks * 32];
            float4 f2 = bW[2 * 128 + ks * 32];
            float4 f3 = bW[3 * 128 + ks * 32];

            // prefetch A fragments for ks+1 (off the MMA critical path)
            if (ks < 3) {
#pragma unroll
                for (int mt = 0; mt < 2; mt++) {
                    uint32_t r0, r1, r2, r3;
                    ldsm_x4(r0, r1, r2, r3,
                            aL + (uint32_t)(mt * 16 * SA_STRIDE * 4 + (ks + 1) * 32));
                    afr[nxt][mt][0] = rna_tf32_u(__uint_as_float(r0));
                    afr[nxt][mt][1] = rna_tf32_u(__uint_as_float(r1));
                    afr[nxt][mt][2] = rna_tf32_u(__uint_as_float(r2));
                    afr[nxt][mt][3] = rna_tf32_u(__uint_as_float(r3));
                }
            }

            const float4 fr[4] = {f0, f1, f2, f3};
#pragma unroll
            for (int p = 0; p < 4; p++) {
                uint32_t b0x = __float_as_uint(fr[p].x), b0y = __float_as_uint(fr[p].y);
                uint32_t b1x = __float_as_uint(fr[p].z), b1y = __float_as_uint(fr[p].w);
                mma_tf32(acc[0][2 * p],     afr[cur][0], b0x, b0y);
                mma_tf32(acc[0][2 * p + 1], afr[cur][0], b1x, b1y);
                mma_tf32(acc[1][2 * p],     afr[cur][1], b0x, b0y);
                mma_tf32(acc[1][2 * p + 1], afr[cur][1], b1x, b1y);
            }
        }
    }

    // ---- epilogue: accum + bias -> gmem (float2, full 32B sectors) ----
    const float* sB = smem + SM_BIAS_OFF;
    const int r0 = warpM + (lane >> 2);
    const int n0 = h * 64 + (lane & 3) * 2;
#pragma unroll
    for (int mt = 0; mt < 2; mt++) {
#pragma unroll
        for (int hh = 0; hh < 2; hh++) {
            int row = r0 + mt * 16 + hh * 8;
            float* orow = o_base + (size_t)row * N_DIM;
#pragma unroll
            for (int nt = 0; nt < 8; nt++) {
                int n = n0 + nt * 8;
                float2 v;
                v.x = acc[mt][nt][hh * 2 + 0] + sB[n];
                v.y = acc[mt][nt][hh * 2 + 1] + sB[n + 1];
                *(float2*)(orow + n) = v;
            }
        }
    }
}

// ===================== launch =====================
extern "C" void kernel_launch(void* const* d_in, const int* in_sizes, int n_in,
                              void* d_out, int out_size) {
    const float* x = (const float*)d_in[0];
    const float* W = (const float*)d_in[1];
    const float* b = (const float*)d_in[2];
    float* out = (float*)d_out;

    cudaFuncSetAttribute(gemm_kernel, cudaFuncAttributeMaxDynamicSharedMemorySize, SMEM_BYTES);

    prep_w_kernel<<<512, 256>>>(W);
    gemm_kernel<<<NUM_CTAS, THREADS, SMEM_BYTES>>>(x, b, out);
}

// round 8
// speedup vs baseline: 1.2775x; 1.1294x over previous
#include <cuda_runtime.h>
#include <cuda_fp16.h>
#include <cstdint>

// ===================== problem constants =====================
// x: 262144 rows x 128; W: (8,128,128); b: (8,128)
// CTA job: 128 rows (M) x 128 cols (N) x K=128. Channel constant per 2 jobs.
#define N_DIM      128
#define K_DIM      128
#define THREADS    256
#define NUM_CTAS   2048
#define K_CHUNK    32
#define NCHUNK     4
#define STAGES     3

// ---- smem layout (floats) ----
// stage: A fp32 chunk 128x32 (linear, stride 32 words) + W fp16 frag image 8KB
#define STAGE_A_FLOATS (128 * 32)              // 4096
#define STAGE_W_FLOATS 2048                    // 8KB fp16 image
#define STAGE_FLOATS   (STAGE_A_FLOATS + STAGE_W_FLOATS)   // 6144
// fp16 A buffer: stride 40 halves (20 words) -> LDSM conflict-free; 2 parity buffers
#define F16_STRIDE_H   40
#define F16_BUF_WORDS  (128 * 20)              // 2560 words = 10KB
#define OFF_F16   (STAGES * STAGE_FLOATS)      // 18432
#define OFF_BIAS  (OFF_F16 + 2 * F16_BUF_WORDS)  // 23552
#define SMEM_FLOATS (OFF_BIAS + 128)
#define SMEM_BYTES  (SMEM_FLOATS * 4)          // 94,720 (x2 CTAs = 190KB <= 228KB)

// ===================== helpers =====================
__device__ __forceinline__ uint32_t smem_u32(const void* p) {
    uint32_t a;
    asm("{ .reg .u64 t; cvta.to.shared.u64 t, %1; cvt.u32.u64 %0, t; }" : "=r"(a) : "l"(p));
    return a;
}
__device__ __forceinline__ void cp_async16(uint32_t dst, const void* src) {
    asm volatile("cp.async.cg.shared.global [%0], [%1], 16;" :: "r"(dst), "l"(src));
}
#define CP_COMMIT()  asm volatile("cp.async.commit_group;" ::: "memory")
#define CP_WAIT(n)   asm volatile("cp.async.wait_group %0;" :: "n"(n) : "memory")

__device__ __forceinline__ void ldsm_x4(uint32_t& r0, uint32_t& r1, uint32_t& r2, uint32_t& r3,
                                        uint32_t addr) {
    asm volatile("ldmatrix.sync.aligned.m8n8.x4.shared.b16 {%0,%1,%2,%3}, [%4];"
                 : "=r"(r0), "=r"(r1), "=r"(r2), "=r"(r3) : "r"(addr));
}

// m16n8k16 fp16 MMA, fp32 accumulate
__device__ __forceinline__ void mma_f16(float* c, const uint32_t* a, uint32_t b0, uint32_t b1) {
    asm volatile(
        "mma.sync.aligned.m16n8k16.row.col.f32.f16.f16.f32 "
        "{%0,%1,%2,%3}, {%4,%5,%6,%7}, {%8,%9}, {%0,%1,%2,%3};"
        : "+f"(c[0]), "+f"(c[1]), "+f"(c[2]), "+f"(c[3])
        : "r"(a[0]), "r"(a[1]), "r"(a[2]), "r"(a[3]), "r"(b0), "r"(b1));
}

// ===================== W fp16 fragment image =====================
// Per (ch, kc): 4096 halves. For 16-col group p (0..7), ks (0..1), lane:
// float4 at fi4 = (p*2+ks)*32+lane = { b0(nt=2p), b1(nt=2p), b0(nt=2p+1), b1(nt=2p+1) }
// where b0 lane l = fp16x2 { W[n][k0], W[n][k0+1] }, n = 16p+8*ntodd+(l>>2),
// k0 = kc*32 + ks*16 + (l&3)*2; b1 = same at k0+8.
__device__ __align__(16) __half g_Wimg[8 * 4 * 4096];

__global__ void prep_w_kernel(const float* __restrict__ W) {
    int idx = blockIdx.x * blockDim.x + threadIdx.x;   // 0 .. 131071
    if (idx >= 8 * 128 * 128) return;
    int ch = idx >> 14;
    int n  = (idx >> 7) & 127;
    int k  = idx & 127;
    int kc = k >> 5;
    int ks = (k >> 4) & 1;
    int bix = (k >> 3) & 1;
    int hsel = k & 1;
    int lane = ((n & 7) << 2) | ((k >> 1) & 3);
    int p = n >> 4;
    int ntodd = (n >> 3) & 1;
    int e = ntodd * 2 + bix;
    int fi4 = (p * 2 + ks) * 32 + lane;
    g_Wimg[(ch * 4 + kc) * 4096 + fi4 * 8 + e * 2 + hsel] = __float2half_rn(W[idx]);
}

// ===================== stage loader (256 threads) =====================
__device__ __forceinline__ void load_stage(uint32_t sm_base, int stage,
                                           const float* a_base, int ch, int kc, int tid) {
    uint32_t sa = sm_base + (uint32_t)(stage * STAGE_FLOATS) * 4u;
    uint32_t sw = sa + STAGE_A_FLOATS * 4u;
    // A fp32 chunk: 128 rows x 32 floats, linear stride 32 -> 1024 16B pieces
#pragma unroll
    for (int j = 0; j < 4; j++) {
        int pid = j * THREADS + tid;
        int r = pid >> 3, pc = pid & 7;
        cp_async16(sa + (uint32_t)(r * 32 + pc * 4) * 4u,
                   a_base + r * K_DIM + kc * K_CHUNK + pc * 4);
    }
    // W fp16 image chunk: 8KB verbatim
    const __half* wsrc = g_Wimg + (ch * 4 + kc) * 4096;
#pragma unroll
    for (int j = 0; j < 2; j++) {
        int pid = j * THREADS + tid;
        cp_async16(sw + (uint32_t)pid * 16u, wsrc + pid * 8);
    }
    CP_COMMIT();
}

// ===================== main GEMM =====================
__global__ __launch_bounds__(THREADS, 2)
void gemm_kernel(const float* __restrict__ x, const float* __restrict__ bias,
                 float* __restrict__ out) {
    extern __shared__ __align__(16) float smem[];
    const uint32_t sm_base = smem_u32(smem);

    const int tid  = threadIdx.x;
    const int lane = tid & 31;
    const int wid  = tid >> 5;
    const int blk  = blockIdx.x;
    const int ch   = (blk >> 1) & 7;

    const float* a_base = x + (size_t)blk * (128 * K_DIM);
    float*       o_base = out + (size_t)blk * (128 * N_DIM);

    if (tid < 128) smem[OFF_BIAS + tid] = bias[ch * 128 + tid];

    // 8 warps: 4 over M (32 rows each), 2 over N (64 cols each)
    const int warpM = (wid >> 1) * 32;
    const int h     = (wid & 1);

    float acc[2][8][4];
#pragma unroll
    for (int mt = 0; mt < 2; mt++)
#pragma unroll
        for (int nt = 0; nt < 8; nt++)
#pragma unroll
            for (int q = 0; q < 4; q++) acc[mt][nt][q] = 0.0f;

    // prologue: prefetch chunks 0,1
    load_stage(sm_base, 0, a_base, ch, 0, tid);
    load_stage(sm_base, 1, a_base, ch, 1, tid);

    // LDSM per-lane base (halves) into fp16 A buffer:
    // row = warpM + (lane&7) + ((lane>>3)&1)*8 ; k-offset halves = (lane>>4)*8
    const uint32_t a_lane_h =
        (uint32_t)((warpM + (lane & 7) + ((lane >> 3) & 1) * 8) * F16_STRIDE_H
                   + (lane >> 4) * 8);
    const uint32_t f16_base = sm_base + OFF_F16 * 4u;
    uint32_t* const f16w = (uint32_t*)(smem + OFF_F16);

#pragma unroll
    for (int kc = 0; kc < NCHUNK; kc++) {
        if (kc < NCHUNK - 1) { CP_WAIT(1); } else { CP_WAIT(0); }
        __syncthreads();
        if (kc + 2 < NCHUNK)
            load_stage(sm_base, (kc + 2) % STAGES, a_base, ch, kc + 2, tid);

        const int s = kc % STAGES;
        const int par = kc & 1;

        // ---- repack: A fp32 stage -> fp16 buffer[par] ----
        {
            const float4* srcA = (const float4*)(smem + s * STAGE_FLOATS);
#pragma unroll
            for (int j = 0; j < 4; j++) {
                int f = j * THREADS + tid;          // 0..1023 float4s (linear)
                float4 v = srcA[f];
                __half2 h0 = __float22half2_rn(make_float2(v.x, v.y));
                __half2 h1 = __float22half2_rn(make_float2(v.z, v.w));
                int r = f >> 3, c8 = (f & 7) * 2;   // word offset within row (20 words)
                uint2 pk;
                pk.x = *(uint32_t*)&h0;
                pk.y = *(uint32_t*)&h1;
                *(uint2*)(f16w + par * F16_BUF_WORDS + r * 20 + c8) = pk;
            }
        }
        __syncthreads();

        // ---- MMA phase: 2 k16-steps ----
        const float4* bW = (const float4*)(smem + s * STAGE_FLOATS + STAGE_A_FLOATS)
                           + h * 256 + lane;
        const uint32_t aL = f16_base + (uint32_t)(par * F16_BUF_WORDS) * 4u + a_lane_h * 2u;

        uint32_t afr[2][2][4];     // [ks parity][mt][4]
        // preload ks=0 fragments
#pragma unroll
        for (int mt = 0; mt < 2; mt++)
            ldsm_x4(afr[0][mt][0], afr[0][mt][1], afr[0][mt][2], afr[0][mt][3],
                    aL + (uint32_t)(mt * 16 * F16_STRIDE_H * 2));

#pragma unroll
        for (int ks = 0; ks < 2; ks++) {
            float4 f0 = bW[0 * 64 + ks * 32];
            float4 f1 = bW[1 * 64 + ks * 32];
            float4 f2 = bW[2 * 64 + ks * 32];
            float4 f3 = bW[3 * 64 + ks * 32];

            if (ks == 0) {
#pragma unroll
                for (int mt = 0; mt < 2; mt++)
                    ldsm_x4(afr[1][mt][0], afr[1][mt][1], afr[1][mt][2], afr[1][mt][3],
                            aL + (uint32_t)((mt * 16 * F16_STRIDE_H + 16) * 2));
            }

            const float4 fr[4] = {f0, f1, f2, f3};
#pragma unroll
            for (int p = 0; p < 4; p++) {
                uint32_t b0e = __float_as_uint(fr[p].x), b1e = __float_as_uint(fr[p].y);
                uint32_t b0o = __float_as_uint(fr[p].z), b1o = __float_as_uint(fr[p].w);
                mma_f16(acc[0][2 * p],     afr[ks][0], b0e, b1e);
                mma_f16(acc[0][2 * p + 1], afr[ks][0], b0o, b1o);
                mma_f16(acc[1][2 * p],     afr[ks][1], b0e, b1e);
                mma_f16(acc[1][2 * p + 1], afr[ks][1], b0o, b1o);
            }
        }
    }

    // ---- epilogue: accum + bias -> gmem (float2, full 32B sectors) ----
    const float* sB = smem + OFF_BIAS;
    const int r0 = warpM + (lane >> 2);
    const int n0 = h * 64 + (lane & 3) * 2;
#pragma unroll
    for (int mt = 0; mt < 2; mt++) {
#pragma unroll
        for (int hh = 0; hh < 2; hh++) {
            int row = r0 + mt * 16 + hh * 8;
            float* orow = o_base + (size_t)row * N_DIM;
#pragma unroll
            for (int nt = 0; nt < 8; nt++) {
                int n = n0 + nt * 8;
                float2 v;
                v.x = acc[mt][nt][hh * 2 + 0] + sB[n];
                v.y = acc[mt][nt][hh * 2 + 1] + sB[n + 1];
                *(float2*)(orow + n) = v;
            }
        }
    }
}

// ===================== launch =====================
extern "C" void kernel_launch(void* const* d_in, const int* in_sizes, int n_in,
                              void* d_out, int out_size) {
    const float* x = (const float*)d_in[0];
    const float* W = (const float*)d_in[1];
    const float* b = (const float*)d_in[2];
    float* out = (float*)d_out;

    cudaFuncSetAttribute(gemm_kernel, cudaFuncAttributeMaxDynamicSharedMemorySize, SMEM_BYTES);

    prep_w_kernel<<<512, 256>>>(W);
    gemm_kernel<<<NUM_CTAS, THREADS, SMEM_BYTES>>>(x, b, out);
}

// round 9
// speedup vs baseline: 1.2918x; 1.0111x over previous
#include <cuda_runtime.h>
#include <cuda_fp16.h>
#include <cstdint>

// ===================== problem constants =====================
// x: 262144 rows x 128; W: (8,128,128); b: (8,128)
// CTA job: 128 rows (M) x 128 cols (N) x K=128. Channel constant per 2 jobs.
#define N_DIM      128
#define K_DIM      128
#define THREADS    256
#define NUM_CTAS   2048
#define K_CHUNK    32
#define NCHUNK     4

// ---- smem layout (floats/words) ----
// [W fp16 frag image: 32KB = 8192 words][A fp16 2 bufs: 2x2560 words][bias 128]
#define OFF_W       0
#define W_IMG_WORDS 8192
#define F16_STRIDE_H 40                       // halves per row -> LDSM conflict-free
#define F16_BUF_WORDS (128 * 20)              // 2560 words = 10KB per parity buf
#define OFF_A       W_IMG_WORDS               // 8192
#define OFF_BIAS    (OFF_A + 2 * F16_BUF_WORDS)   // 13312
#define SMEM_FLOATS (OFF_BIAS + 128)
#define SMEM_BYTES  (SMEM_FLOATS * 4)         // 53,760 (x2 CTAs = 107.5KB)

// ===================== helpers =====================
__device__ __forceinline__ uint32_t smem_u32(const void* p) {
    uint32_t a;
    asm("{ .reg .u64 t; cvta.to.shared.u64 t, %1; cvt.u32.u64 %0, t; }" : "=r"(a) : "l"(p));
    return a;
}
__device__ __forceinline__ void cp_async16(uint32_t dst, const void* src) {
    asm volatile("cp.async.cg.shared.global [%0], [%1], 16;" :: "r"(dst), "l"(src));
}
#define CP_COMMIT()  asm volatile("cp.async.commit_group;" ::: "memory")
#define CP_WAIT(n)   asm volatile("cp.async.wait_group %0;" :: "n"(n) : "memory")

__device__ __forceinline__ void ldsm_x4(uint32_t& r0, uint32_t& r1, uint32_t& r2, uint32_t& r3,
                                        uint32_t addr) {
    asm volatile("ldmatrix.sync.aligned.m8n8.x4.shared.b16 {%0,%1,%2,%3}, [%4];"
                 : "=r"(r0), "=r"(r1), "=r"(r2), "=r"(r3) : "r"(addr));
}

// m16n8k16 fp16 MMA, fp32 accumulate
__device__ __forceinline__ void mma_f16(float* c, const uint32_t* a, uint32_t b0, uint32_t b1) {
    asm volatile(
        "mma.sync.aligned.m16n8k16.row.col.f32.f16.f16.f32 "
        "{%0,%1,%2,%3}, {%4,%5,%6,%7}, {%8,%9}, {%0,%1,%2,%3};"
        : "+f"(c[0]), "+f"(c[1]), "+f"(c[2]), "+f"(c[3])
        : "r"(a[0]), "r"(a[1]), "r"(a[2]), "r"(a[3]), "r"(b0), "r"(b1));
}

// ===================== W fp16 fragment image =====================
// Per (ch, kc): 4096 halves (512 float4s). fi4 = (p*2+ks)*32+lane holds
// { b0(nt=2p), b1(nt=2p), b0(nt=2p+1), b1(nt=2p+1) } fp16x2 fragments
// (validated in round 8).
__device__ __align__(16) __half g_Wimg[8 * 4 * 4096];

__global__ void prep_w_kernel(const float* __restrict__ W) {
    int idx = blockIdx.x * blockDim.x + threadIdx.x;   // 0 .. 131071
    if (idx >= 8 * 128 * 128) return;
    int ch = idx >> 14;
    int n  = (idx >> 7) & 127;
    int k  = idx & 127;
    int kc = k >> 5;
    int ks = (k >> 4) & 1;
    int bix = (k >> 3) & 1;
    int hsel = k & 1;
    int lane = ((n & 7) << 2) | ((k >> 1) & 3);
    int p = n >> 4;
    int ntodd = (n >> 3) & 1;
    int e = ntodd * 2 + bix;
    int fi4 = (p * 2 + ks) * 32 + lane;
    g_Wimg[(ch * 4 + kc) * 4096 + fi4 * 8 + e * 2 + hsel] = __float2half_rn(W[idx]);
}

// ===================== main GEMM =====================
__global__ __launch_bounds__(THREADS, 2)
void gemm_kernel(const float* __restrict__ x, const float* __restrict__ bias,
                 float* __restrict__ out) {
    extern __shared__ __align__(16) float smem[];
    const uint32_t sm_base = smem_u32(smem);

    const int tid  = threadIdx.x;
    const int lane = tid & 31;
    const int wid  = tid >> 5;
    const int blk  = blockIdx.x;
    const int ch   = (blk >> 1) & 7;

    const float* a_base = x + (size_t)blk * (128 * K_DIM);
    float*       o_base = out + (size_t)blk * (128 * N_DIM);

    // ---- prologue: W image (32KB, L2-resident) via cp.async; bias; A chunk 0 ----
    {
        const __half* wsrc = g_Wimg + ch * 16384;
        uint32_t sw = sm_base + OFF_W * 4u;
#pragma unroll
        for (int j = 0; j < 8; j++) {
            int pid = j * THREADS + tid;
            cp_async16(sw + (uint32_t)pid * 16u, wsrc + pid * 8);
        }
        CP_COMMIT();
    }
    if (tid < 128) smem[OFF_BIAS + tid] = bias[ch * 128 + tid];

    // 8 warps: 4 over M (32 rows each), 2 over N (64 cols each)
    const int warpM = (wid >> 1) * 32;
    const int h     = (wid & 1);

    float acc[2][8][4];
#pragma unroll
    for (int mt = 0; mt < 2; mt++)
#pragma unroll
        for (int nt = 0; nt < 8; nt++)
#pragma unroll
            for (int q = 0; q < 4; q++) acc[mt][nt][q] = 0.0f;

    uint32_t* const abufw = (uint32_t*)(smem + OFF_A);   // word view of fp16 bufs

    // per-thread A piece coordinates: pid = i*256+tid -> row pid>>3, 4-col group pid&7
    const int arow = tid >> 3;          // rows handled: arow, arow+32, arow+64, arow+96
    const int apc  = tid & 7;

    // LDG chunk 0
    float4 v[4];
#pragma unroll
    for (int i = 0; i < 4; i++)
        v[i] = *(const float4*)(a_base + (size_t)(arow + i * 32) * K_DIM + apc * 4);

    CP_WAIT(0);
    __syncthreads();                     // W image + bias visible

    // STS chunk 0 -> buf 0
#pragma unroll
    for (int i = 0; i < 4; i++) {
        __half2 h0 = __float22half2_rn(make_float2(v[i].x, v[i].y));
        __half2 h1 = __float22half2_rn(make_float2(v[i].z, v[i].w));
        uint2 pk; pk.x = *(uint32_t*)&h0; pk.y = *(uint32_t*)&h1;
        *(uint2*)(abufw + (arow + i * 32) * 20 + apc * 2) = pk;
    }
    __syncthreads();

    // LDSM per-lane base (halves): row = warpM + (lane&7) + ((lane>>3)&1)*8, +8 halves per k16-half
    const uint32_t a_lane_h =
        (uint32_t)((warpM + (lane & 7) + ((lane >> 3) & 1) * 8) * F16_STRIDE_H
                   + (lane >> 4) * 8);
    const uint32_t f16_base = sm_base + OFF_A * 4u;

#pragma unroll
    for (int kc = 0; kc < NCHUNK; kc++) {
        const int par = kc & 1;

        // LDG next chunk (covered by the MMA block below)
        if (kc < NCHUNK - 1) {
#pragma unroll
            for (int i = 0; i < 4; i++)
                v[i] = *(const float4*)(a_base + (size_t)(arow + i * 32) * K_DIM
                                        + (kc + 1) * K_CHUNK + apc * 4);
        }

        // ---- MMA phase on buf[par], W frags for this kc ----
        const float4* bW = (const float4*)(smem + OFF_W) + kc * 512 + h * 256 + lane;
        const uint32_t aL = f16_base + (uint32_t)(par * F16_BUF_WORDS) * 4u + a_lane_h * 2u;

        uint32_t afr[2][2][4];
#pragma unroll
        for (int mt = 0; mt < 2; mt++)
            ldsm_x4(afr[0][mt][0], afr[0][mt][1], afr[0][mt][2], afr[0][mt][3],
                    aL + (uint32_t)(mt * 16 * F16_STRIDE_H * 2));

#pragma unroll
        for (int ks = 0; ks < 2; ks++) {
            float4 f0 = bW[0 * 64 + ks * 32];
            float4 f1 = bW[1 * 64 + ks * 32];
            float4 f2 = bW[2 * 64 + ks * 32];
            float4 f3 = bW[3 * 64 + ks * 32];

            if (ks == 0) {
#pragma unroll
                for (int mt = 0; mt < 2; mt++)
                    ldsm_x4(afr[1][mt][0], afr[1][mt][1], afr[1][mt][2], afr[1][mt][3],
                            aL + (uint32_t)((mt * 16 * F16_STRIDE_H + 16) * 2));
            }

            const float4 fr[4] = {f0, f1, f2, f3};
#pragma unroll
            for (int p = 0; p < 4; p++) {
                uint32_t b0e = __float_as_uint(fr[p].x), b1e = __float_as_uint(fr[p].y);
                uint32_t b0o = __float_as_uint(fr[p].z), b1o = __float_as_uint(fr[p].w);
                mma_f16(acc[0][2 * p],     afr[ks][0], b0e, b1e);
                mma_f16(acc[0][2 * p + 1], afr[ks][0], b0o, b1o);
                mma_f16(acc[1][2 * p],     afr[ks][1], b0e, b1e);
                mma_f16(acc[1][2 * p + 1], afr[ks][1], b0o, b1o);
            }
        }

        // ---- cvt + STS next chunk into opposite buffer; single barrier ----
        if (kc < NCHUNK - 1) {
            const int npar = par ^ 1;
#pragma unroll
            for (int i = 0; i < 4; i++) {
                __half2 h0 = __float22half2_rn(make_float2(v[i].x, v[i].y));
                __half2 h1 = __float22half2_rn(make_float2(v[i].z, v[i].w));
                uint2 pk; pk.x = *(uint32_t*)&h0; pk.y = *(uint32_t*)&h1;
                *(uint2*)(abufw + npar * F16_BUF_WORDS + (arow + i * 32) * 20 + apc * 2) = pk;
            }
            __syncthreads();
        }
    }

    // ---- epilogue: accum + bias -> gmem (float2, full 32B sectors) ----
    const float* sB = smem + OFF_BIAS;
    const int r0 = warpM + (lane >> 2);
    const int n0 = h * 64 + (lane & 3) * 2;
#pragma unroll
    for (int mt = 0; mt < 2; mt++) {
#pragma unroll
        for (int hh = 0; hh < 2; hh++) {
            int row = r0 + mt * 16 + hh * 8;
            float* orow = o_base + (size_t)row * N_DIM;
#pragma unroll
            for (int nt = 0; nt < 8; nt++) {
                int n = n0 + nt * 8;
                float2 vv;
                vv.x = acc[mt][nt][hh * 2 + 0] + sB[n];
                vv.y = acc[mt][nt][hh * 2 + 1] + sB[n + 1];
                *(float2*)(orow + n) = vv;
            }
        }
    }
}

// ===================== launch =====================
extern "C" void kernel_launch(void* const* d_in, const int* in_sizes, int n_in,
                              void* d_out, int out_size) {
    const float* x = (const float*)d_in[0];
    const float* W = (const float*)d_in[1];
    const float* b = (const float*)d_in[2];
    float* out = (float*)d_out;

    cudaFuncSetAttribute(gemm_kernel, cudaFuncAttributeMaxDynamicSharedMemorySize, SMEM_BYTES);

    prep_w_kernel<<<512, 256>>>(W);
    gemm_kernel<<<NUM_CTAS, THREADS, SMEM_BYTES>>>(x, b, out);
}

// round 10
// speedup vs baseline: 1.2925x; 1.0006x over previous
#include <cuda_runtime.h>
#include <cuda_fp16.h>
#include <cstdint>

// ===================== problem constants =====================
// x: 262144 rows x 128; W: (8,128,128); b: (8,128)
// CTA job: 128 rows (M) x 128 cols (N) x K=128, one job per CTA.
#define N_DIM      128
#define K_DIM      128
#define THREADS    256
#define NUM_CTAS   2048

// ---- smem layout (32-bit words) ----
// [W fp16 frag image: 8192 words][A fp16 whole job: 128 rows x 68 words][bias 128]
#define OFF_W        0
#define W_IMG_WORDS  8192
#define F16A_WSTRIDE 68                       // words per A row (136 halves) -> LDSM conflict-free
#define A_BUF_WORDS  (128 * F16A_WSTRIDE)     // 8704
#define OFF_A        W_IMG_WORDS              // 8192
#define OFF_BIAS     (OFF_A + A_BUF_WORDS)    // 16896
#define SMEM_FLOATS  (OFF_BIAS + 128)
#define SMEM_BYTES   (SMEM_FLOATS * 4)        // 68,096 (x2 CTAs = 136KB <= 228KB)

// ===================== helpers =====================
__device__ __forceinline__ uint32_t smem_u32(const void* p) {
    uint32_t a;
    asm("{ .reg .u64 t; cvta.to.shared.u64 t, %1; cvt.u32.u64 %0, t; }" : "=r"(a) : "l"(p));
    return a;
}
__device__ __forceinline__ void cp_async16(uint32_t dst, const void* src) {
    asm volatile("cp.async.cg.shared.global [%0], [%1], 16;" :: "r"(dst), "l"(src));
}
#define CP_COMMIT()  asm volatile("cp.async.commit_group;" ::: "memory")
#define CP_WAIT(n)   asm volatile("cp.async.wait_group %0;" :: "n"(n) : "memory")

__device__ __forceinline__ void ldsm_x4(uint32_t& r0, uint32_t& r1, uint32_t& r2, uint32_t& r3,
                                        uint32_t addr) {
    asm volatile("ldmatrix.sync.aligned.m8n8.x4.shared.b16 {%0,%1,%2,%3}, [%4];"
                 : "=r"(r0), "=r"(r1), "=r"(r2), "=r"(r3) : "r"(addr));
}

// m16n8k16 fp16 MMA, fp32 accumulate
__device__ __forceinline__ void mma_f16(float* c, const uint32_t* a, uint32_t b0, uint32_t b1) {
    asm volatile(
        "mma.sync.aligned.m16n8k16.row.col.f32.f16.f16.f32 "
        "{%0,%1,%2,%3}, {%4,%5,%6,%7}, {%8,%9}, {%0,%1,%2,%3};"
        : "+f"(c[0]), "+f"(c[1]), "+f"(c[2]), "+f"(c[3])
        : "r"(a[0]), "r"(a[1]), "r"(a[2]), "r"(a[3]), "r"(b0), "r"(b1));
}

// ===================== W fp16 fragment image (validated rounds 8-9) =====================
// Per (ch, kc): 4096 halves (512 float4s). fi4 = (p*2+ks)*32+lane holds
// { b0(nt=2p), b1(nt=2p), b0(nt=2p+1), b1(nt=2p+1) } fp16x2 fragments.
__device__ __align__(16) __half g_Wimg[8 * 4 * 4096];

__global__ void prep_w_kernel(const float* __restrict__ W) {
    int idx = blockIdx.x * blockDim.x + threadIdx.x;   // 0 .. 131071
    if (idx >= 8 * 128 * 128) return;
    int ch = idx >> 14;
    int n  = (idx >> 7) & 127;
    int k  = idx & 127;
    int kc = k >> 5;
    int ks = (k >> 4) & 1;
    int bix = (k >> 3) & 1;
    int hsel = k & 1;
    int lane = ((n & 7) << 2) | ((k >> 1) & 3);
    int p = n >> 4;
    int ntodd = (n >> 3) & 1;
    int e = ntodd * 2 + bix;
    int fi4 = (p * 2 + ks) * 32 + lane;
    g_Wimg[(ch * 4 + kc) * 4096 + fi4 * 8 + e * 2 + hsel] = __float2half_rn(W[idx]);
}

// ===================== main GEMM =====================
__global__ __launch_bounds__(THREADS, 2)
void gemm_kernel(const float* __restrict__ x, const float* __restrict__ bias,
                 float* __restrict__ out) {
    extern __shared__ __align__(16) float smem[];
    const uint32_t sm_base = smem_u32(smem);

    const int tid  = threadIdx.x;
    const int lane = tid & 31;
    const int wid  = tid >> 5;
    const int blk  = blockIdx.x;
    const int ch   = (blk >> 1) & 7;

    const float* a_base = x + (size_t)blk * (128 * K_DIM);
    float*       o_base = out + (size_t)blk * (128 * N_DIM);

    // ---- load phase: whole-job A via LDG (16 float4/thread), W image via cp.async ----
    float4 v[16];
#pragma unroll
    for (int i = 0; i < 16; i++) {
        int pid = i * THREADS + tid;          // row = pid>>5, col4 = pid&31 (coalesced)
        v[i] = *(const float4*)(a_base + (size_t)(pid >> 5) * K_DIM + (pid & 31) * 4);
    }
    {
        const __half* wsrc = g_Wimg + ch * 16384;
        uint32_t sw = sm_base + OFF_W * 4u;
#pragma unroll
        for (int j = 0; j < 8; j++) {
            int pid = j * THREADS + tid;
            cp_async16(sw + (uint32_t)pid * 16u, wsrc + pid * 8);
        }
        CP_COMMIT();
    }
    if (tid < 128) smem[OFF_BIAS + tid] = bias[ch * 128 + tid];

    // cvt fp32->fp16 and store whole A tile (stride 68 words per row)
    uint32_t* const abufw = (uint32_t*)(smem + OFF_A);
#pragma unroll
    for (int i = 0; i < 16; i++) {
        int pid = i * THREADS + tid;
        int r = pid >> 5, c4 = pid & 31;
        __half2 h0 = __float22half2_rn(make_float2(v[i].x, v[i].y));
        __half2 h1 = __float22half2_rn(make_float2(v[i].z, v[i].w));
        uint2 pk; pk.x = *(uint32_t*)&h0; pk.y = *(uint32_t*)&h1;
        *(uint2*)(abufw + r * F16A_WSTRIDE + c4 * 2) = pk;
    }

    CP_WAIT(0);
    __syncthreads();          // the ONLY barrier: W image + A tile + bias visible

    // 8 warps: 4 over M (32 rows each), 2 over N (64 cols each)
    const int warpM = (wid >> 1) * 32;
    const int h     = (wid & 1);

    float acc[2][8][4];
#pragma unroll
    for (int mt = 0; mt < 2; mt++)
#pragma unroll
        for (int nt = 0; nt < 8; nt++)
#pragma unroll
            for (int q = 0; q < 4; q++) acc[mt][nt][q] = 0.0f;

    // LDSM per-lane byte address: row = warpM + (lane&7) + ((lane>>3)&1)*8,
    // +8 halves for lanes 16-31 (second k-half of the k16 step)
    const uint32_t aL0 = sm_base + OFF_A * 4u +
        (uint32_t)(((warpM + (lane & 7) + ((lane >> 3) & 1) * 8) * 136
                    + (lane >> 4) * 8) * 2);

    // ---- single uninterrupted MMA block: 4 chunks x 2 k16-steps, no barriers ----
#pragma unroll
    for (int kc = 0; kc < 4; kc++) {
        const float4* bW = (const float4*)(smem + OFF_W) + kc * 512 + h * 256 + lane;
        const uint32_t aL = aL0 + (uint32_t)(kc * 32 * 2);   // +32 halves per chunk

        uint32_t afr[2][2][4];
#pragma unroll
        for (int mt = 0; mt < 2; mt++)
            ldsm_x4(afr[0][mt][0], afr[0][mt][1], afr[0][mt][2], afr[0][mt][3],
                    aL + (uint32_t)(mt * 16 * 136 * 2));

#pragma unroll
        for (int ks = 0; ks < 2; ks++) {
            float4 f0 = bW[0 * 64 + ks * 32];
            float4 f1 = bW[1 * 64 + ks * 32];
            float4 f2 = bW[2 * 64 + ks * 32];
            float4 f3 = bW[3 * 64 + ks * 32];

            if (ks == 0) {
#pragma unroll
                for (int mt = 0; mt < 2; mt++)
                    ldsm_x4(afr[1][mt][0], afr[1][mt][1], afr[1][mt][2], afr[1][mt][3],
                            aL + (uint32_t)((mt * 16 * 136 + 16) * 2));
            }

            const float4 fr[4] = {f0, f1, f2, f3};
#pragma unroll
            for (int p = 0; p < 4; p++) {
                uint32_t b0e = __float_as_uint(fr[p].x), b1e = __float_as_uint(fr[p].y);
                uint32_t b0o = __float_as_uint(fr[p].z), b1o = __float_as_uint(fr[p].w);
                mma_f16(acc[0][2 * p],     afr[ks][0], b0e, b1e);
                mma_f16(acc[0][2 * p + 1], afr[ks][0], b0o, b1o);
                mma_f16(acc[1][2 * p],     afr[ks][1], b0e, b1e);
                mma_f16(acc[1][2 * p + 1], afr[ks][1], b0o, b1o);
            }
        }
    }

    // ---- epilogue: accum + bias -> gmem (float2, full 32B sectors) ----
    const float* sB = smem + OFF_BIAS;
    const int r0 = warpM + (lane >> 2);
    const int n0 = h * 64 + (lane & 3) * 2;
#pragma unroll
    for (int mt = 0; mt < 2; mt++) {
#pragma unroll
        for (int hh = 0; hh < 2; hh++) {
            int row = r0 + mt * 16 + hh * 8;
            float* orow = o_base + (size_t)row * N_DIM;
#pragma unroll
            for (int nt = 0; nt < 8; nt++) {
                int n = n0 + nt * 8;
                float2 vv;
                vv.x = acc[mt][nt][hh * 2 + 0] + sB[n];
                vv.y = acc[mt][nt][hh * 2 + 1] + sB[n + 1];
                *(float2*)(orow + n) = vv;
            }
        }
    }
}

// ===================== launch =====================
extern "C" void kernel_launch(void* const* d_in, const int* in_sizes, int n_in,
                              void* d_out, int out_size) {
    const float* x = (const float*)d_in[0];
    const float* W = (const float*)d_in[1];
    const float* b = (const float*)d_in[2];
    float* out = (float*)d_out;

    cudaFuncSetAttribute(gemm_kernel, cudaFuncAttributeMaxDynamicSharedMemorySize, SMEM_BYTES);

    prep_w_kernel<<<512, 256>>>(W);
    gemm_kernel<<<NUM_CTAS, THREADS, SMEM_BYTES>>>(x, b, out);
}